// round 16
// baseline (speedup 1.0000x reference)
#include <cuda_runtime.h>
#include <cuda_fp16.h>
#include <math.h>
#include <stdint.h>

#define SEQ 8192
#define DIM 768
#define DIM3 (3 * DIM)   // 2304

// ---------------- scratch (__device__ globals; no allocations allowed) -----
__device__ __align__(128) __half g_X16 [(size_t)SEQ * DIM];
__device__ __align__(128) __half g_Wc16[(size_t)DIM3 * DIM];       // [Wq;Wk;Wv]
__device__ __align__(128) __half g_QKV [(size_t)SEQ * DIM3];       // packed Q|K|V
__device__ __align__(128) __half g_V16t[(size_t)DIM * SEQ];
__device__ __align__(128) __half g_E16 [(size_t)SEQ * SEQ];        // exp(scores), fp16
__device__ __align__(128) float  g_rowsum[SEQ];                    // per-row exp sums
__device__ __align__(128) __half g_Opart[3][(size_t)SEQ * DIM];    // PV split-K partials (fp16)

// ---------------- helpers ----------------------------------------------------
__device__ __forceinline__ uint32_t smem_u32(const void* p) {
    uint32_t a;
    asm("{ .reg .u64 t; cvta.to.shared.u64 t, %1; cvt.u32.u64 %0, t; }"
        : "=r"(a) : "l"(p));
    return a;
}

#define MMA16816(d, a, b0, b1)                                                 \
    asm volatile(                                                              \
        "mma.sync.aligned.m16n8k16.row.col.f32.f16.f16.f32 "                   \
        "{%0,%1,%2,%3}, {%4,%5,%6,%7}, {%8,%9}, {%0,%1,%2,%3};"                \
        : "+f"((d)[0]), "+f"((d)[1]), "+f"((d)[2]), "+f"((d)[3])               \
        : "r"((a)[0]), "r"((a)[1]), "r"((a)[2]), "r"((a)[3]),                  \
          "r"(b0), "r"(b1))

#define LDSM_X4(r, addr)                                                       \
    asm volatile("ldmatrix.sync.aligned.m8n8.x4.shared.b16 {%0,%1,%2,%3}, [%4];" \
        : "=r"((r)[0]), "=r"((r)[1]), "=r"((r)[2]), "=r"((r)[3]) : "r"(addr))

#define CP_ASYNC16(saddr, gptr)                                                \
    asm volatile("cp.async.cg.shared.global [%0], [%1], 16;"                   \
        :: "r"(saddr), "l"(gptr))

// ---------------- GEMM: C[M,N] = alpha * A[M,*] * B[N,*]^T  (fp16 in)
// CTA tile 128x128, BK=64 halves, 8 warps each 32x64, 3-stage cp.async,
// 2 CTAs/SM (validated optimum: at the smem fragment-traffic roofline).
// gridDim.z = K-splits: split z covers [z*Ke, min((z+1)*Ke, Ktot)),
// writes C + z*csplit (non-uniform last split supported via Ktot clamp).
// MODE: 1 -> fp16 C;
//       2 -> fp16 exp(alpha*acc) C + per-row atomic sum into rowsum[].
#define BM 128
#define BN 128
#define BKH 64                     // halves per K tile (128 bytes per row)
#define TILE_BYTES (128 * 128)     // 16 KB per operand stage
#define NSTAGE 3
#define GEMM_SMEM (2 * NSTAGE * TILE_BYTES)   // 96 KB

template <int MODE>
__global__ void __launch_bounds__(256, 2)
gemm_f16_mma(const __half* __restrict__ A, const __half* __restrict__ B,
             void* __restrict__ Cv, int N, int Ke, int Ktot,
             int lda, int ldb, int ldc, float alpha, size_t csplit,
             float* __restrict__ rowsum)
{
    extern __shared__ char smem[];
    const uint32_t sA = smem_u32(smem);                    // NSTAGE stages A
    const uint32_t sB = sA + NSTAGE * TILE_BYTES;          // NSTAGE stages B

    const int tid  = threadIdx.x;
    const int lane = tid & 31;
    const int wid  = tid >> 5;
    const int warp_m = (wid & 3) * 32;
    const int warp_n = (wid >> 2) * 64;
    const int bm = blockIdx.y * BM;
    const int bn = blockIdx.x * BN;
    const int koff = blockIdx.z * Ke;
    const int kspan = (Ktot - koff < Ke) ? (Ktot - koff) : Ke;
    const int nk = kspan / BKH;

    float acc[2][8][4];
#pragma unroll
    for (int i = 0; i < 2; ++i)
#pragma unroll
        for (int j = 0; j < 8; ++j)
#pragma unroll
            for (int k = 0; k < 4; ++k) acc[i][j][k] = 0.f;

#define LOAD_STAGE(kt, st)                                                     \
    do {                                                                       \
        _Pragma("unroll")                                                      \
        for (int i = 0; i < 4; ++i) {                                          \
            int idx = tid + i * 256;                                           \
            int row = idx >> 3;                                                \
            int ch  = idx & 7;                                                 \
            int pch = ch ^ (row & 7);                                          \
            const __half* gA = A + (size_t)(bm + row) * lda + koff + (kt) * BKH + ch * 8; \
            CP_ASYNC16(sA + (st) * TILE_BYTES + row * 128 + pch * 16, gA);     \
            const __half* gB = B + (size_t)(bn + row) * ldb + koff + (kt) * BKH + ch * 8; \
            CP_ASYNC16(sB + (st) * TILE_BYTES + row * 128 + pch * 16, gB);     \
        }                                                                      \
        asm volatile("cp.async.commit_group;");                                \
    } while (0)

    LOAD_STAGE(0, 0);
    if (1 < nk) LOAD_STAGE(1, 1);
    else        asm volatile("cp.async.commit_group;");

    for (int kt = 0; kt < nk; ++kt) {
        const int st = kt % NSTAGE;
        if (kt + 1 < nk) {
            asm volatile("cp.async.wait_group 1;");
        } else {
            asm volatile("cp.async.wait_group 0;");
        }
        // Single barrier per k-tile (3-stage ring orders stage reuse).
        __syncthreads();
        if (kt + 2 < nk) LOAD_STAGE(kt + 2, (kt + 2) % NSTAGE);

        const uint32_t aBase = sA + st * TILE_BYTES;
        const uint32_t bBase = sB + st * TILE_BYTES;
#pragma unroll
        for (int ks = 0; ks < 4; ++ks) {
            uint32_t af[2][4];
#pragma unroll
            for (int mt = 0; mt < 2; ++mt) {
                int row = warp_m + mt * 16 + (lane & 7) + ((lane >> 3) & 1) * 8;
                int ch  = ks * 2 + (lane >> 4);
                uint32_t ad = aBase + row * 128 + ((ch ^ (row & 7)) * 16);
                LDSM_X4(af[mt], ad);
            }
#pragma unroll
            for (int ng = 0; ng < 4; ++ng) {
                int nrow = warp_n + ng * 16 + (lane & 7) + ((lane >> 4) & 1) * 8;
                int ch   = ks * 2 + ((lane >> 3) & 1);
                uint32_t bd = bBase + nrow * 128 + ((ch ^ (nrow & 7)) * 16);
                uint32_t bf[4];
                LDSM_X4(bf, bd);
#pragma unroll
                for (int mt = 0; mt < 2; ++mt) {
                    MMA16816(acc[mt][ng * 2],     af[mt], bf[0], bf[1]);
                    MMA16816(acc[mt][ng * 2 + 1], af[mt], bf[2], bf[3]);
                }
            }
        }
    }

    // epilogue
    float lsum[2][2];
    if (MODE == 2) {
        lsum[0][0] = lsum[0][1] = lsum[1][0] = lsum[1][1] = 0.f;
    }
#pragma unroll
    for (int mt = 0; mt < 2; ++mt) {
        const int r0 = bm + warp_m + mt * 16 + (lane >> 2);
#pragma unroll
        for (int nt = 0; nt < 8; ++nt) {
            const int c = bn + warp_n + nt * 8 + (lane & 3) * 2;
            if (MODE == 2) {
                __half* C = (__half*)Cv;
                float e0 = __expf(acc[mt][nt][0] * alpha);
                float e1 = __expf(acc[mt][nt][1] * alpha);
                float e2 = __expf(acc[mt][nt][2] * alpha);
                float e3 = __expf(acc[mt][nt][3] * alpha);
                lsum[mt][0] += e0 + e1;
                lsum[mt][1] += e2 + e3;
                *(__half2*)(C + (size_t)r0 * ldc + c)       = __floats2half2_rn(e0, e1);
                *(__half2*)(C + (size_t)(r0 + 8) * ldc + c) = __floats2half2_rn(e2, e3);
            } else {
                __half* C = (__half*)Cv + blockIdx.z * csplit;
                __half2 v0 = __floats2half2_rn(acc[mt][nt][0] * alpha,
                                               acc[mt][nt][1] * alpha);
                __half2 v1 = __floats2half2_rn(acc[mt][nt][2] * alpha,
                                               acc[mt][nt][3] * alpha);
                *(__half2*)(C + (size_t)r0 * ldc + c)       = v0;
                *(__half2*)(C + (size_t)(r0 + 8) * ldc + c) = v1;
            }
        }
    }
    if (MODE == 2) {
        // 4 lanes (lane&3) share each row: butterfly-reduce, leader atomicAdd.
#pragma unroll
        for (int mt = 0; mt < 2; ++mt) {
#pragma unroll
            for (int h = 0; h < 2; ++h) {
                float s = lsum[mt][h];
                s += __shfl_xor_sync(0xffffffffu, s, 1);
                s += __shfl_xor_sync(0xffffffffu, s, 2);
                if ((lane & 3) == 0) {
                    int row = bm + warp_m + mt * 16 + (lane >> 2) + h * 8;
                    atomicAdd(rowsum + row, s);
                }
            }
        }
    }
#undef LOAD_STAGE
}

// ---------------- fused fp32 -> fp16 conversion (X + Wq/Wk/Wv) ---------------
__device__ __forceinline__ uint32_t pack2(__half a, __half b) {
    __half2 h = __halves2half2(a, b);
    return *(uint32_t*)&h;
}

#define NX4 ((size_t)SEQ * DIM / 4)    // float4 groups in X
#define NW4 ((size_t)DIM * DIM / 4)    // per weight matrix

__global__ void __launch_bounds__(256)
conv_all(const float* __restrict__ X,
         const float* __restrict__ Wq, const float* __restrict__ Wk,
         const float* __restrict__ Wv,
         __half* __restrict__ X16, __half* __restrict__ Wc16,
         float* __restrict__ rowsum)
{
    const size_t gtid = (size_t)blockIdx.x * 256 + threadIdx.x;
    if (gtid < SEQ) rowsum[gtid] = 0.f;

    const size_t total = NX4 + 3 * NW4;
    for (size_t i = gtid; i < total; i += (size_t)gridDim.x * 256) {
        const float* src;
        __half* dst;
        size_t j;
        if (i < NX4) {
            src = X;  dst = X16;  j = i;
        } else {
            size_t w = i - NX4;
            int m = (int)(w / NW4);
            j = w % NW4;
            src = (m == 0) ? Wq : (m == 1) ? Wk : Wv;
            dst = Wc16 + (size_t)m * (NW4 * 4);
        }
        float4 v = *(const float4*)(src + j * 4);
        uint2 u = make_uint2(
            pack2(__float2half_rn(v.x), __float2half_rn(v.y)),
            pack2(__float2half_rn(v.z), __float2half_rn(v.w)));
        *(uint2*)(dst + j * 4) = u;
    }
}

// ---------------- vectorized fp16 transpose ---------------------------------
// src[R x C, row stride srcld] -> dst[C x R]; 64x64 tiles, uint4 (8-half)
// global loads AND stores, transpose staged through padded SMEM.
__global__ void __launch_bounds__(256)
trans_half_v(const __half* __restrict__ src, __half* __restrict__ dst,
             int R, int C, int srcld)
{
    __shared__ __half t[64][72];   // +8 halves pad (16B) kills bank conflicts
    const int tid = threadIdx.x;
    const int bx = blockIdx.x;     // 64-col tile (C dim)
    const int by = blockIdx.y;     // 64-row tile (R dim)

    // load: 64 rows x 8 uint4 groups = 512; 2 per thread
#pragma unroll
    for (int i = 0; i < 2; ++i) {
        const int v  = tid + i * 256;
        const int r  = v >> 3;          // 0..63
        const int c8 = (v & 7) * 8;     // 0..56
        uint4 x = *(const uint4*)(src + (size_t)(by * 64 + r) * srcld
                                      + bx * 64 + c8);
        const __half* h = (const __half*)&x;
#pragma unroll
        for (int j = 0; j < 8; ++j) t[c8 + j][r] = h[j];
    }
    __syncthreads();

    // store: dst row = bx*64 + c, cols by*64 + r8..r8+7
#pragma unroll
    for (int i = 0; i < 2; ++i) {
        const int v  = tid + i * 256;
        const int c  = v >> 3;
        const int r8 = (v & 7) * 8;
        uint4 x;
        __half* h = (__half*)&x;
#pragma unroll
        for (int j = 0; j < 8; ++j) h[j] = t[c][r8 + j];
        *(uint4*)(dst + (size_t)(bx * 64 + c) * R + by * 64 + r8) = x;
    }
}

// ---------------- split-K reduction + softmax normalization ------------------
// O[i] = (h0+h1+h2)[i] / rowsum[i / DIM]   (fp16 partials, fp32 math)
__global__ void __launch_bounds__(256)
add3h_scale(const __half* __restrict__ a0, const __half* __restrict__ a1,
            const __half* __restrict__ a2,
            const float* __restrict__ rowsum, float* __restrict__ o, size_t n)
{
    const size_t n4 = n / 4;
    for (size_t i = (size_t)blockIdx.x * 256 + threadIdx.x; i < n4;
         i += (size_t)gridDim.x * 256) {
        uint2 u0 = *(const uint2*)(a0 + i * 4);
        uint2 u1 = *(const uint2*)(a1 + i * 4);
        uint2 u2 = *(const uint2*)(a2 + i * 4);
        float2 x0 = __half22float2(*(__half2*)&u0.x);
        float2 x1 = __half22float2(*(__half2*)&u0.y);
        float2 y0 = __half22float2(*(__half2*)&u1.x);
        float2 y1 = __half22float2(*(__half2*)&u1.y);
        float2 z0 = __half22float2(*(__half2*)&u2.x);
        float2 z1 = __half22float2(*(__half2*)&u2.y);
        const int row = (int)((i * 4) / DIM);
        const float inv = __frcp_rn(rowsum[row]);
        float4 r;
        r.x = (x0.x + y0.x + z0.x) * inv;
        r.y = (x0.y + y0.y + z0.y) * inv;
        r.z = (x1.x + y1.x + z1.x) * inv;
        r.w = (x1.y + y1.y + z1.y) * inv;
        *(float4*)(o + i * 4) = r;
    }
}

// ---------------------------------------------------------------------------
extern "C" void kernel_launch(void* const* d_in, const int* in_sizes, int n_in,
                              void* d_out, int out_size)
{
    const float* X  = (const float*)d_in[0];
    const float* Wq = (const float*)d_in[1];
    const float* Wk = (const float*)d_in[2];
    const float* Wv = (const float*)d_in[3];
    float* O = (float*)d_out;

    __half *X16, *Wc16, *QKV, *V16t, *E16, *Op;
    float *rowsum;
    cudaGetSymbolAddress((void**)&X16,    g_X16);
    cudaGetSymbolAddress((void**)&Wc16,   g_Wc16);
    cudaGetSymbolAddress((void**)&QKV,    g_QKV);
    cudaGetSymbolAddress((void**)&V16t,   g_V16t);
    cudaGetSymbolAddress((void**)&E16,    g_E16);
    cudaGetSymbolAddress((void**)&rowsum, g_rowsum);
    cudaGetSymbolAddress((void**)&Op,     g_Opart);

    cudaFuncSetAttribute(gemm_f16_mma<1>,
                         cudaFuncAttributeMaxDynamicSharedMemorySize, GEMM_SMEM);
    cudaFuncSetAttribute(gemm_f16_mma<2>,
                         cudaFuncAttributeMaxDynamicSharedMemorySize, GEMM_SMEM);

    const float inv_sqrt_d = 0.03608439182435161f;  // 1/sqrt(768)
    const dim3 blk(256);
    const size_t OSZ = (size_t)SEQ * DIM;

    // 1: fused conversions (X + 3 W matrices) + rowsum zeroing
    conv_all<<<592, blk>>>(X, Wq, Wk, Wv, X16, Wc16, rowsum);

    // 2: fused projection: QKV[8192 x 2304] = X @ Wc^T  (1152 CTAs)
    gemm_f16_mma<1><<<dim3(DIM3 / BN, SEQ / BM, 1), blk, GEMM_SMEM>>>(
        X16, Wc16, QKV, DIM3, DIM, DIM, DIM, DIM, DIM3, 1.f, 0, nullptr);

    // 3: E = exp((Q @ K^T)/sqrt(d)), fp16; per-row sums via atomics (4096 CTAs)
    gemm_f16_mma<2><<<dim3(SEQ / BN, SEQ / BM, 1), blk, GEMM_SMEM>>>(
        QKV, QKV + DIM, E16, SEQ, DIM, DIM, DIM3, DIM3, SEQ, inv_sqrt_d, 0, rowsum);

    // 4: V transpose (strided slice of QKV) -> V16t [768 x 8192], vectorized
    trans_half_v<<<dim3(DIM / 64, SEQ / 64), blk>>>(QKV + 2 * DIM, V16t,
                                                    SEQ, DIM, DIM3);

    // 5: O' = E @ V: non-uniform split-K=3 (Ke=2752; last 2688), fp16 partials
    gemm_f16_mma<1><<<dim3(DIM / BN, SEQ / BM, 3), blk, GEMM_SMEM>>>(
        E16, V16t, Op, DIM, 2752, SEQ, SEQ, SEQ, DIM, 1.f, OSZ, nullptr);

    // 6: O = (sum of 3 fp16 partials) / rowsum[row]
    add3h_scale<<<1024, blk>>>(Op, Op + OSZ, Op + 2 * OSZ, rowsum, O, OSZ);
}

// round 17
// speedup vs baseline: 1.0202x; 1.0202x over previous
#include <cuda_runtime.h>
#include <cuda_fp16.h>
#include <math.h>
#include <stdint.h>

#define SEQ 8192
#define DIM 768
#define DIM3 (3 * DIM)   // 2304

// ---------------- scratch (__device__ globals; no allocations allowed) -----
__device__ __align__(128) __half g_X16 [(size_t)SEQ * DIM];
__device__ __align__(128) __half g_Wc16[(size_t)DIM3 * DIM];       // [Wq;Wk;Wv]
__device__ __align__(128) __half g_QKV [(size_t)SEQ * DIM3];       // packed Q|K|(V unused)
__device__ __align__(128) __half g_V16t[(size_t)DIM * SEQ];
__device__ __align__(128) __half g_E16 [(size_t)SEQ * SEQ];        // exp(scores), fp16
__device__ __align__(128) float  g_rowsum[SEQ];                    // per-row exp sums
__device__ __align__(128) __half g_Opart[3][(size_t)SEQ * DIM];    // PV split-K partials (fp16)

// ---------------- helpers ----------------------------------------------------
__device__ __forceinline__ uint32_t smem_u32(const void* p) {
    uint32_t a;
    asm("{ .reg .u64 t; cvta.to.shared.u64 t, %1; cvt.u32.u64 %0, t; }"
        : "=r"(a) : "l"(p));
    return a;
}

#define MMA16816(d, a, b0, b1)                                                 \
    asm volatile(                                                              \
        "mma.sync.aligned.m16n8k16.row.col.f32.f16.f16.f32 "                   \
        "{%0,%1,%2,%3}, {%4,%5,%6,%7}, {%8,%9}, {%0,%1,%2,%3};"                \
        : "+f"((d)[0]), "+f"((d)[1]), "+f"((d)[2]), "+f"((d)[3])               \
        : "r"((a)[0]), "r"((a)[1]), "r"((a)[2]), "r"((a)[3]),                  \
          "r"(b0), "r"(b1))

#define LDSM_X4(r, addr)                                                       \
    asm volatile("ldmatrix.sync.aligned.m8n8.x4.shared.b16 {%0,%1,%2,%3}, [%4];" \
        : "=r"((r)[0]), "=r"((r)[1]), "=r"((r)[2]), "=r"((r)[3]) : "r"(addr))

#define CP_ASYNC16(saddr, gptr)                                                \
    asm volatile("cp.async.cg.shared.global [%0], [%1], 16;"                   \
        :: "r"(saddr), "l"(gptr))

// ---------------- GEMM: C[M,N] = alpha * A[M,*] * B[N,*]^T  (fp16 in)
// CTA tile 128x128, BK=64 halves, 8 warps each 32x64, 3-stage cp.async,
// 2 CTAs/SM (validated optimum: at the smem fragment-traffic roofline).
// gridDim.z = K-splits: split z covers [z*Ke, min((z+1)*Ke, Ktot)),
// writes C + z*csplit (non-uniform last split supported via Ktot clamp).
// MODE: 1 -> fp16 C; if vt != nullptr, tiles with bn >= vtcol store
//       TRANSPOSED into vt[(c - vtcol)][row] (row stride SEQ) instead of C.
//       2 -> fp16 exp(alpha*acc) C + per-row atomic sum into rowsum[].
#define BM 128
#define BN 128
#define BKH 64                     // halves per K tile (128 bytes per row)
#define TILE_BYTES (128 * 128)     // 16 KB per operand stage
#define NSTAGE 3
#define GEMM_SMEM (2 * NSTAGE * TILE_BYTES)   // 96 KB

template <int MODE>
__global__ void __launch_bounds__(256, 2)
gemm_f16_mma(const __half* __restrict__ A, const __half* __restrict__ B,
             void* __restrict__ Cv, int N, int Ke, int Ktot,
             int lda, int ldb, int ldc, float alpha, size_t csplit,
             float* __restrict__ rowsum, __half* __restrict__ vt, int vtcol)
{
    extern __shared__ char smem[];
    const uint32_t sA = smem_u32(smem);                    // NSTAGE stages A
    const uint32_t sB = sA + NSTAGE * TILE_BYTES;          // NSTAGE stages B

    const int tid  = threadIdx.x;
    const int lane = tid & 31;
    const int wid  = tid >> 5;
    const int warp_m = (wid & 3) * 32;
    const int warp_n = (wid >> 2) * 64;
    const int bm = blockIdx.y * BM;
    const int bn = blockIdx.x * BN;
    const int koff = blockIdx.z * Ke;
    const int kspan = (Ktot - koff < Ke) ? (Ktot - koff) : Ke;
    const int nk = kspan / BKH;

    float acc[2][8][4];
#pragma unroll
    for (int i = 0; i < 2; ++i)
#pragma unroll
        for (int j = 0; j < 8; ++j)
#pragma unroll
            for (int k = 0; k < 4; ++k) acc[i][j][k] = 0.f;

#define LOAD_STAGE(kt, st)                                                     \
    do {                                                                       \
        _Pragma("unroll")                                                      \
        for (int i = 0; i < 4; ++i) {                                          \
            int idx = tid + i * 256;                                           \
            int row = idx >> 3;                                                \
            int ch  = idx & 7;                                                 \
            int pch = ch ^ (row & 7);                                          \
            const __half* gA = A + (size_t)(bm + row) * lda + koff + (kt) * BKH + ch * 8; \
            CP_ASYNC16(sA + (st) * TILE_BYTES + row * 128 + pch * 16, gA);     \
            const __half* gB = B + (size_t)(bn + row) * ldb + koff + (kt) * BKH + ch * 8; \
            CP_ASYNC16(sB + (st) * TILE_BYTES + row * 128 + pch * 16, gB);     \
        }                                                                      \
        asm volatile("cp.async.commit_group;");                                \
    } while (0)

    LOAD_STAGE(0, 0);
    if (1 < nk) LOAD_STAGE(1, 1);
    else        asm volatile("cp.async.commit_group;");

    for (int kt = 0; kt < nk; ++kt) {
        const int st = kt % NSTAGE;
        if (kt + 1 < nk) {
            asm volatile("cp.async.wait_group 1;");
        } else {
            asm volatile("cp.async.wait_group 0;");
        }
        // Single barrier per k-tile (3-stage ring orders stage reuse).
        __syncthreads();
        if (kt + 2 < nk) LOAD_STAGE(kt + 2, (kt + 2) % NSTAGE);

        const uint32_t aBase = sA + st * TILE_BYTES;
        const uint32_t bBase = sB + st * TILE_BYTES;
#pragma unroll
        for (int ks = 0; ks < 4; ++ks) {
            uint32_t af[2][4];
#pragma unroll
            for (int mt = 0; mt < 2; ++mt) {
                int row = warp_m + mt * 16 + (lane & 7) + ((lane >> 3) & 1) * 8;
                int ch  = ks * 2 + (lane >> 4);
                uint32_t ad = aBase + row * 128 + ((ch ^ (row & 7)) * 16);
                LDSM_X4(af[mt], ad);
            }
#pragma unroll
            for (int ng = 0; ng < 4; ++ng) {
                int nrow = warp_n + ng * 16 + (lane & 7) + ((lane >> 4) & 1) * 8;
                int ch   = ks * 2 + ((lane >> 3) & 1);
                uint32_t bd = bBase + nrow * 128 + ((ch ^ (nrow & 7)) * 16);
                uint32_t bf[4];
                LDSM_X4(bf, bd);
#pragma unroll
                for (int mt = 0; mt < 2; ++mt) {
                    MMA16816(acc[mt][ng * 2],     af[mt], bf[0], bf[1]);
                    MMA16816(acc[mt][ng * 2 + 1], af[mt], bf[2], bf[3]);
                }
            }
        }
    }

    // epilogue
    float lsum[2][2];
    if (MODE == 2) {
        lsum[0][0] = lsum[0][1] = lsum[1][0] = lsum[1][1] = 0.f;
    }
    const bool to_vt = (MODE == 1) && (vt != nullptr) && (bn >= vtcol);
#pragma unroll
    for (int mt = 0; mt < 2; ++mt) {
        const int r0 = bm + warp_m + mt * 16 + (lane >> 2);
#pragma unroll
        for (int nt = 0; nt < 8; ++nt) {
            const int c = bn + warp_n + nt * 8 + (lane & 3) * 2;
            if (MODE == 2) {
                __half* C = (__half*)Cv;
                float e0 = __expf(acc[mt][nt][0] * alpha);
                float e1 = __expf(acc[mt][nt][1] * alpha);
                float e2 = __expf(acc[mt][nt][2] * alpha);
                float e3 = __expf(acc[mt][nt][3] * alpha);
                lsum[mt][0] += e0 + e1;
                lsum[mt][1] += e2 + e3;
                *(__half2*)(C + (size_t)r0 * ldc + c)       = __floats2half2_rn(e0, e1);
                *(__half2*)(C + (size_t)(r0 + 8) * ldc + c) = __floats2half2_rn(e2, e3);
            } else if (to_vt) {
                // transposed store: vt[(c - vtcol)][row], row stride SEQ
                const int vc = c - vtcol;
                __half* row0 = vt + (size_t)vc * SEQ;
                __half* row1 = vt + (size_t)(vc + 1) * SEQ;
                row0[r0]     = __float2half_rn(acc[mt][nt][0]);
                row1[r0]     = __float2half_rn(acc[mt][nt][1]);
                row0[r0 + 8] = __float2half_rn(acc[mt][nt][2]);
                row1[r0 + 8] = __float2half_rn(acc[mt][nt][3]);
            } else {
                __half* C = (__half*)Cv + blockIdx.z * csplit;
                __half2 v0 = __floats2half2_rn(acc[mt][nt][0] * alpha,
                                               acc[mt][nt][1] * alpha);
                __half2 v1 = __floats2half2_rn(acc[mt][nt][2] * alpha,
                                               acc[mt][nt][3] * alpha);
                *(__half2*)(C + (size_t)r0 * ldc + c)       = v0;
                *(__half2*)(C + (size_t)(r0 + 8) * ldc + c) = v1;
            }
        }
    }
    if (MODE == 2) {
        // 4 lanes (lane&3) share each row: butterfly-reduce, leader atomicAdd.
#pragma unroll
        for (int mt = 0; mt < 2; ++mt) {
#pragma unroll
            for (int h = 0; h < 2; ++h) {
                float s = lsum[mt][h];
                s += __shfl_xor_sync(0xffffffffu, s, 1);
                s += __shfl_xor_sync(0xffffffffu, s, 2);
                if ((lane & 3) == 0) {
                    int row = bm + warp_m + mt * 16 + (lane >> 2) + h * 8;
                    atomicAdd(rowsum + row, s);
                }
            }
        }
    }
#undef LOAD_STAGE
}

// ---------------- fused fp32 -> fp16 conversion (X + Wq/Wk/Wv) ---------------
__device__ __forceinline__ uint32_t pack2(__half a, __half b) {
    __half2 h = __halves2half2(a, b);
    return *(uint32_t*)&h;
}

#define NX4 ((size_t)SEQ * DIM / 4)    // float4 groups in X
#define NW4 ((size_t)DIM * DIM / 4)    // per weight matrix

__global__ void __launch_bounds__(256)
conv_all(const float* __restrict__ X,
         const float* __restrict__ Wq, const float* __restrict__ Wk,
         const float* __restrict__ Wv,
         __half* __restrict__ X16, __half* __restrict__ Wc16,
         float* __restrict__ rowsum)
{
    const size_t gtid = (size_t)blockIdx.x * 256 + threadIdx.x;
    if (gtid < SEQ) rowsum[gtid] = 0.f;

    const size_t total = NX4 + 3 * NW4;
    for (size_t i = gtid; i < total; i += (size_t)gridDim.x * 256) {
        const float* src;
        __half* dst;
        size_t j;
        if (i < NX4) {
            src = X;  dst = X16;  j = i;
        } else {
            size_t w = i - NX4;
            int m = (int)(w / NW4);
            j = w % NW4;
            src = (m == 0) ? Wq : (m == 1) ? Wk : Wv;
            dst = Wc16 + (size_t)m * (NW4 * 4);
        }
        float4 v = *(const float4*)(src + j * 4);
        uint2 u = make_uint2(
            pack2(__float2half_rn(v.x), __float2half_rn(v.y)),
            pack2(__float2half_rn(v.z), __float2half_rn(v.w)));
        *(uint2*)(dst + j * 4) = u;
    }
}

// ---------------- split-K reduction + softmax normalization ------------------
// O[i] = (h0+h1+h2)[i] / rowsum[i / DIM]   (fp16 partials, fp32 math)
__global__ void __launch_bounds__(256)
add3h_scale(const __half* __restrict__ a0, const __half* __restrict__ a1,
            const __half* __restrict__ a2,
            const float* __restrict__ rowsum, float* __restrict__ o, size_t n)
{
    const size_t n4 = n / 4;
    for (size_t i = (size_t)blockIdx.x * 256 + threadIdx.x; i < n4;
         i += (size_t)gridDim.x * 256) {
        uint2 u0 = *(const uint2*)(a0 + i * 4);
        uint2 u1 = *(const uint2*)(a1 + i * 4);
        uint2 u2 = *(const uint2*)(a2 + i * 4);
        float2 x0 = __half22float2(*(__half2*)&u0.x);
        float2 x1 = __half22float2(*(__half2*)&u0.y);
        float2 y0 = __half22float2(*(__half2*)&u1.x);
        float2 y1 = __half22float2(*(__half2*)&u1.y);
        float2 z0 = __half22float2(*(__half2*)&u2.x);
        float2 z1 = __half22float2(*(__half2*)&u2.y);
        const int row = (int)((i * 4) / DIM);
        const float inv = __frcp_rn(rowsum[row]);
        float4 r;
        r.x = (x0.x + y0.x + z0.x) * inv;
        r.y = (x0.y + y0.y + z0.y) * inv;
        r.z = (x1.x + y1.x + z1.x) * inv;
        r.w = (x1.y + y1.y + z1.y) * inv;
        *(float4*)(o + i * 4) = r;
    }
}

// ---------------------------------------------------------------------------
extern "C" void kernel_launch(void* const* d_in, const int* in_sizes, int n_in,
                              void* d_out, int out_size)
{
    const float* X  = (const float*)d_in[0];
    const float* Wq = (const float*)d_in[1];
    const float* Wk = (const float*)d_in[2];
    const float* Wv = (const float*)d_in[3];
    float* O = (float*)d_out;

    __half *X16, *Wc16, *QKV, *V16t, *E16, *Op;
    float *rowsum;
    cudaGetSymbolAddress((void**)&X16,    g_X16);
    cudaGetSymbolAddress((void**)&Wc16,   g_Wc16);
    cudaGetSymbolAddress((void**)&QKV,    g_QKV);
    cudaGetSymbolAddress((void**)&V16t,   g_V16t);
    cudaGetSymbolAddress((void**)&E16,    g_E16);
    cudaGetSymbolAddress((void**)&rowsum, g_rowsum);
    cudaGetSymbolAddress((void**)&Op,     g_Opart);

    cudaFuncSetAttribute(gemm_f16_mma<1>,
                         cudaFuncAttributeMaxDynamicSharedMemorySize, GEMM_SMEM);
    cudaFuncSetAttribute(gemm_f16_mma<2>,
                         cudaFuncAttributeMaxDynamicSharedMemorySize, GEMM_SMEM);

    const float inv_sqrt_d = 0.03608439182435161f;  // 1/sqrt(768)
    const dim3 blk(256);
    const size_t OSZ = (size_t)SEQ * DIM;

    // 1: fused conversions (X + 3 W matrices) + rowsum zeroing
    conv_all<<<592, blk>>>(X, Wq, Wk, Wv, X16, Wc16, rowsum);

    // 2: fused projection: QKV = X @ Wc^T; V tiles (bn >= 1536) stored
    //    TRANSPOSED directly into V16t (no separate transpose kernel)
    gemm_f16_mma<1><<<dim3(DIM3 / BN, SEQ / BM, 1), blk, GEMM_SMEM>>>(
        X16, Wc16, QKV, DIM3, DIM, DIM, DIM, DIM, DIM3, 1.f, 0,
        nullptr, V16t, 2 * DIM);

    // 3: E = exp((Q @ K^T)/sqrt(d)), fp16; per-row sums via atomics (4096 CTAs)
    gemm_f16_mma<2><<<dim3(SEQ / BN, SEQ / BM, 1), blk, GEMM_SMEM>>>(
        QKV, QKV + DIM, E16, SEQ, DIM, DIM, DIM3, DIM3, SEQ, inv_sqrt_d, 0,
        rowsum, nullptr, 0);

    // 4: O' = E @ V: non-uniform split-K=3 (Ke=2752; last 2688), fp16 partials
    gemm_f16_mma<1><<<dim3(DIM / BN, SEQ / BM, 3), blk, GEMM_SMEM>>>(
        E16, V16t, Op, DIM, 2752, SEQ, SEQ, SEQ, DIM, 1.f, OSZ,
        nullptr, nullptr, 0);

    // 5: O = (sum of 3 fp16 partials) / rowsum[row]
    add3h_scale<<<1024, blk>>>(Op, Op + OSZ, Op + 2 * OSZ, rowsum, O, OSZ);
}